// round 1
// baseline (speedup 1.0000x reference)
#include <cuda_runtime.h>
#include <cuda_bf16.h>
#include <math.h>

#define BATCH 2
#define NSEQ  2048
#define DMODEL 1024
#define NLAYER 2
#define VOCAB 50257
#define EPS_F 1e-6f
#define MTOK (BATCH*NSEQ)   // 4096

// ---------------- scratch (device globals; no allocations allowed) ----------
__device__ float g_x  [MTOK*DMODEL];
__device__ float g_q  [MTOK*DMODEL];
__device__ float g_k  [MTOK*DMODEL];
__device__ float g_v  [MTOK*DMODEL];
__device__ float g_ctx[MTOK*DMODEL];
__device__ float g_kv [BATCH*DMODEL*DMODEL];
__device__ float g_ks [BATCH*DMODEL];
__device__ float g_z  [MTOK];

// ---------------- embedding gather ------------------------------------------
__global__ void gather_kernel(const int* __restrict__ ids,
                              const float* __restrict__ emb,
                              float* __restrict__ x) {
    int row = blockIdx.x;                // 0..MTOK-1
    int id  = ids[row];
    const float4* src = (const float4*)(emb + (long)id * DMODEL);
    float4*       dst = (float4*)(x + (long)row * DMODEL);
    for (int i = threadIdx.x; i < DMODEL/4; i += blockDim.x) dst[i] = src[i];
}

// ---------------- Ksum[b,d] = sum_n K[b,n,d] + EPS (deterministic) ----------
__global__ void ksum_kernel(const float* __restrict__ Kbuf,
                            float* __restrict__ ks) {
    int d = blockIdx.x * 256 + threadIdx.x;     // 0..1023
    int b = blockIdx.y;
    const float* p = Kbuf + (long)b * NSEQ * DMODEL + d;
    float acc = 0.f;
    #pragma unroll 8
    for (int n = 0; n < NSEQ; n++) acc += p[(long)n * DMODEL];
    ks[b * DMODEL + d] = acc + EPS_F;
}

// ---------------- Z[b,n] = Q[b,n,:] . Ksum[b,:] -----------------------------
__global__ void z_kernel(const float* __restrict__ Q,
                         const float* __restrict__ ks,
                         float* __restrict__ z) {
    int row  = blockIdx.x * 8 + (threadIdx.x >> 5);   // warp per row
    int lane = threadIdx.x & 31;
    int b    = row / NSEQ;
    const float* q = Q  + (long)row * DMODEL;
    const float* s = ks + (long)b   * DMODEL;
    float acc = 0.f;
    #pragma unroll 4
    for (int i = lane; i < DMODEL; i += 32) acc += q[i] * s[i];
    #pragma unroll
    for (int o = 16; o; o >>= 1) acc += __shfl_xor_sync(0xffffffffu, acc, o);
    if (lane == 0) z[row] = acc;
}

// ---------------- pooled = x[:, -1, :] --------------------------------------
__global__ void pooled_kernel(const float* __restrict__ x,
                              float* __restrict__ out) {
    int i = blockIdx.x * blockDim.x + threadIdx.x;   // 0..BATCH*DMODEL-1
    if (i >= BATCH * DMODEL) return;
    int b = i / DMODEL, d = i % DMODEL;
    out[i] = x[((long)b * NSEQ + (NSEQ - 1)) * DMODEL + d];
}

// ---------------- generic fp32 GEMM -----------------------------------------
// C[M,N] = epilogue( A_eff[M,K] * B_eff[K,N] )
//   AKM=true : A stored [M,K] row-major (lda=K)  -> transpose into As[k][m]
//   AKM=false: A stored [K,M] row-major (lda=M)  -> direct As[k][m]
//   BKM=true : B stored [N,K] row-major (ldb=K)  -> transpose into Bs[k][n]
//   BKM=false: B stored [K,N] row-major (ldb=N)  -> direct Bs[k][n]
// epilogue: optional rowdiv (C /= rowdiv[m]), optional bias[n], optional elu+1
#define BM 128
#define BN 128
#define BK 16

template<bool AKM, bool BKM>
__global__ __launch_bounds__(256, 2)
void sgemm_kernel(int M, int N, int K,
                  const float* __restrict__ A, int lda, long sA,
                  const float* __restrict__ Bm, int ldb, long sB,
                  float* __restrict__ C, int ldc, long sC,
                  const float* __restrict__ bias,
                  const float* __restrict__ rowdiv, long sR,
                  int act)
{
    __shared__ float As[BK][BM + 4];
    __shared__ float Bs[BK][BN + 4];

    int tid = threadIdx.x;
    int tx = tid & 15, ty = tid >> 4;
    int mBase = blockIdx.y * BM;
    int nBase = blockIdx.x * BN;
    int zb = blockIdx.z;
    A  += (long)zb * sA;
    Bm += (long)zb * sB;
    C  += (long)zb * sC;
    if (rowdiv) rowdiv += (long)zb * sR;

    float acc[8][8];
    #pragma unroll
    for (int i = 0; i < 8; i++)
        #pragma unroll
        for (int j = 0; j < 8; j++) acc[i][j] = 0.f;

    for (int k0 = 0; k0 < K; k0 += BK) {
        // ---- load A tile ----
        if (AKM) {
            #pragma unroll
            for (int it = 0; it < 2; it++) {
                int idx = tid + it * 256;
                int r  = idx >> 2;             // 0..127 (m within tile)
                int c4 = (idx & 3) << 2;       // 0,4,8,12 (k within tile)
                int gm = mBase + r;
                float4 v = make_float4(0.f, 0.f, 0.f, 0.f);
                if (gm < M) v = *(const float4*)(A + (long)gm * lda + k0 + c4);
                As[c4 + 0][r] = v.x; As[c4 + 1][r] = v.y;
                As[c4 + 2][r] = v.z; As[c4 + 3][r] = v.w;
            }
        } else {
            #pragma unroll
            for (int it = 0; it < 2; it++) {
                int idx = tid + it * 256;
                int kr = idx >> 5;             // 0..15
                int mc = (idx & 31) << 2;      // 0..124
                int gm = mBase + mc;
                float4 v = make_float4(0.f, 0.f, 0.f, 0.f);
                if (gm < M) v = *(const float4*)(A + (long)(k0 + kr) * lda + gm);
                *(float4*)&As[kr][mc] = v;
            }
        }
        // ---- load B tile ----
        if (BKM) {
            #pragma unroll
            for (int it = 0; it < 2; it++) {
                int idx = tid + it * 256;
                int r  = idx >> 2;             // 0..127 (n within tile)
                int c4 = (idx & 3) << 2;
                int gn = nBase + r;
                float4 v = make_float4(0.f, 0.f, 0.f, 0.f);
                if (gn < N) v = *(const float4*)(Bm + (long)gn * ldb + k0 + c4);
                Bs[c4 + 0][r] = v.x; Bs[c4 + 1][r] = v.y;
                Bs[c4 + 2][r] = v.z; Bs[c4 + 3][r] = v.w;
            }
        } else {
            #pragma unroll
            for (int it = 0; it < 2; it++) {
                int idx = tid + it * 256;
                int kr = idx >> 5;
                int nc = (idx & 31) << 2;
                int gn = nBase + nc;
                float4 v = make_float4(0.f, 0.f, 0.f, 0.f);
                if (gn + 3 < N) {
                    v = *(const float4*)(Bm + (long)(k0 + kr) * ldb + gn);
                } else if (gn < N) {
                    const float* p = Bm + (long)(k0 + kr) * ldb;
                    v.x = p[gn];
                    if (gn + 1 < N) v.y = p[gn + 1];
                    if (gn + 2 < N) v.z = p[gn + 2];
                }
                *(float4*)&Bs[kr][nc] = v;
            }
        }
        __syncthreads();
        // ---- compute ----
        #pragma unroll
        for (int kk = 0; kk < BK; kk++) {
            float af[8], bf[8];
            #pragma unroll
            for (int i = 0; i < 8; i++) af[i] = As[kk][ty * 8 + i];
            #pragma unroll
            for (int j = 0; j < 8; j++) bf[j] = Bs[kk][tx * 8 + j];
            #pragma unroll
            for (int i = 0; i < 8; i++)
                #pragma unroll
                for (int j = 0; j < 8; j++)
                    acc[i][j] = fmaf(af[i], bf[j], acc[i][j]);
        }
        __syncthreads();
    }

    // ---- epilogue ----
    #pragma unroll
    for (int i = 0; i < 8; i++) {
        int gm = mBase + ty * 8 + i;
        if (gm >= M) continue;
        float rs = 1.0f;
        if (rowdiv) rs = 1.0f / rowdiv[gm];
        #pragma unroll
        for (int j = 0; j < 8; j++) {
            int gn = nBase + tx * 8 + j;
            if (gn >= N) continue;
            float c = acc[i][j] * rs;
            if (bias) c += bias[gn];
            if (act) c = (c > 0.f) ? (c + 1.0f) : expf(c);
            C[(long)gm * ldc + gn] = c;
        }
    }
}

// ---------------- driver -----------------------------------------------------
extern "C" void kernel_launch(void* const* d_in, const int* in_sizes, int n_in,
                              void* d_out, int out_size) {
    const int*   ids = (const int*)  d_in[0];
    const float* emb = (const float*)d_in[1];
    const float* Wq  = (const float*)d_in[2];
    const float* bq  = (const float*)d_in[3];
    const float* Wk  = (const float*)d_in[4];
    const float* bk  = (const float*)d_in[5];
    const float* Wv  = (const float*)d_in[6];
    const float* bv  = (const float*)d_in[7];
    const float* Wo  = (const float*)d_in[8];
    const float* bo  = (const float*)d_in[9];
    const float* Wh  = (const float*)d_in[10];
    const float* bh  = (const float*)d_in[11];

    float* logits = (float*)d_out;
    float* pooled = logits + (long)MTOK * VOCAB;

    float *x, *q, *kbuf, *vbuf, *ctx, *kv, *ks, *z;
    cudaGetSymbolAddress((void**)&x,    g_x);
    cudaGetSymbolAddress((void**)&q,    g_q);
    cudaGetSymbolAddress((void**)&kbuf, g_k);
    cudaGetSymbolAddress((void**)&vbuf, g_v);
    cudaGetSymbolAddress((void**)&ctx,  g_ctx);
    cudaGetSymbolAddress((void**)&kv,   g_kv);
    cudaGetSymbolAddress((void**)&ks,   g_ks);
    cudaGetSymbolAddress((void**)&z,    g_z);

    // x = emb[ids]
    gather_kernel<<<MTOK, 256>>>(ids, emb, x);

    const long sTok = (long)NSEQ * DMODEL;   // per-batch token-matrix stride
    const long sKV  = (long)DMODEL * DMODEL;

    for (int l = 0; l < NLAYER; l++) {
        const float* wq = Wq + (long)l * DMODEL * DMODEL;
        const float* wk = Wk + (long)l * DMODEL * DMODEL;
        const float* wv = Wv + (long)l * DMODEL * DMODEL;
        const float* wo = Wo + (long)l * DMODEL * DMODEL;
        const float* bql = bq + (long)l * DMODEL;
        const float* bkl = bk + (long)l * DMODEL;
        const float* bvl = bv + (long)l * DMODEL;
        const float* bol = bo + (long)l * DMODEL;

        dim3 gQ(DMODEL / BN, MTOK / BM, 1);          // (8, 32)
        // Q = elu(x Wq^T + bq) + 1 ; K likewise ; V = x Wv^T + bv
        sgemm_kernel<true, true><<<gQ, 256>>>(MTOK, DMODEL, DMODEL,
            x, DMODEL, 0, wq, DMODEL, 0, q,    DMODEL, 0, bql, nullptr, 0, 1);
        sgemm_kernel<true, true><<<gQ, 256>>>(MTOK, DMODEL, DMODEL,
            x, DMODEL, 0, wk, DMODEL, 0, kbuf, DMODEL, 0, bkl, nullptr, 0, 1);
        sgemm_kernel<true, true><<<gQ, 256>>>(MTOK, DMODEL, DMODEL,
            x, DMODEL, 0, wv, DMODEL, 0, vbuf, DMODEL, 0, bvl, nullptr, 0, 0);

        // KV[b] = K[b]^T V[b]   (TN, reduction over NSEQ)
        dim3 gKV(DMODEL / BN, DMODEL / BM, BATCH);   // (8, 8, 2)
        sgemm_kernel<false, false><<<gKV, 256>>>(DMODEL, DMODEL, NSEQ,
            kbuf, DMODEL, sTok, vbuf, DMODEL, sTok, kv, DMODEL, sKV,
            nullptr, nullptr, 0, 0);

        // Ksum + eps
        ksum_kernel<<<dim3(DMODEL / 256, BATCH), 256>>>(kbuf, ks);
        // Z = Q . Ksum
        z_kernel<<<MTOK / 8, 256>>>(q, ks, z);

        // ctx[b] = (Q[b] @ KV[b]) / Z   (NN)
        dim3 gC(DMODEL / BN, NSEQ / BM, BATCH);      // (8, 16, 2)
        sgemm_kernel<true, false><<<gC, 256>>>(NSEQ, DMODEL, DMODEL,
            q, DMODEL, sTok, kv, DMODEL, sKV, ctx, DMODEL, sTok,
            nullptr, z, NSEQ, 0);

        // x = ctx Wo^T + bo
        sgemm_kernel<true, true><<<gQ, 256>>>(MTOK, DMODEL, DMODEL,
            ctx, DMODEL, 0, wo, DMODEL, 0, x, DMODEL, 0, bol, nullptr, 0, 0);
    }

    // logits = x W_head^T + b_head
    dim3 gH((VOCAB + BN - 1) / BN, MTOK / BM, 1);    // (393, 32)
    sgemm_kernel<true, true><<<gH, 256>>>(MTOK, VOCAB, DMODEL,
        x, DMODEL, 0, Wh, DMODEL, 0, logits, VOCAB, 0, bh, nullptr, 0, 0);

    // pooled = x[:, -1]
    pooled_kernel<<<(BATCH * DMODEL + 255) / 256, 256>>>(x, pooled);
}

// round 2
// speedup vs baseline: 1.0007x; 1.0007x over previous
#include <cuda_runtime.h>
#include <cuda_bf16.h>
#include <math.h>

#define BATCH 2
#define NSEQ  2048
#define DMODEL 1024
#define NLAYER 2
#define VOCAB 50257
#define EPS_F 1e-6f
#define MTOK (BATCH*NSEQ)   // 4096

// ---------------- scratch (device globals; no allocations allowed) ----------
__device__ float g_x  [MTOK*DMODEL];
__device__ float g_q  [MTOK*DMODEL];
__device__ float g_k  [MTOK*DMODEL];
__device__ float g_v  [MTOK*DMODEL];
__device__ float g_ctx[MTOK*DMODEL];
__device__ float g_kv [BATCH*DMODEL*DMODEL];
__device__ float g_ks [BATCH*DMODEL];
__device__ float g_z  [MTOK];

// ---------------- embedding gather ------------------------------------------
__global__ void gather_kernel(const int* __restrict__ ids,
                              const float* __restrict__ emb,
                              float* __restrict__ x) {
    int row = blockIdx.x;                // 0..MTOK-1
    int id  = ids[row];
    const float4* src = (const float4*)(emb + (long)id * DMODEL);
    float4*       dst = (float4*)(x + (long)row * DMODEL);
    for (int i = threadIdx.x; i < DMODEL/4; i += blockDim.x) dst[i] = src[i];
}

// ---------------- Ksum[b,d] = sum_n K[b,n,d] + EPS (deterministic) ----------
__global__ void ksum_kernel(const float* __restrict__ Kbuf,
                            float* __restrict__ ks) {
    int d = blockIdx.x * 256 + threadIdx.x;     // 0..1023
    int b = blockIdx.y;
    const float* p = Kbuf + (long)b * NSEQ * DMODEL + d;
    float acc = 0.f;
    #pragma unroll 8
    for (int n = 0; n < NSEQ; n++) acc += p[(long)n * DMODEL];
    ks[b * DMODEL + d] = acc + EPS_F;
}

// ---------------- Z[b,n] = Q[b,n,:] . Ksum[b,:] -----------------------------
__global__ void z_kernel(const float* __restrict__ Q,
                         const float* __restrict__ ks,
                         float* __restrict__ z) {
    int row  = blockIdx.x * 8 + (threadIdx.x >> 5);   // warp per row
    int lane = threadIdx.x & 31;
    int b    = row / NSEQ;
    const float* q = Q  + (long)row * DMODEL;
    const float* s = ks + (long)b   * DMODEL;
    float acc = 0.f;
    #pragma unroll 4
    for (int i = lane; i < DMODEL; i += 32) acc += q[i] * s[i];
    #pragma unroll
    for (int o = 16; o; o >>= 1) acc += __shfl_xor_sync(0xffffffffu, acc, o);
    if (lane == 0) z[row] = acc;
}

// ---------------- pooled = x[:, -1, :] --------------------------------------
__global__ void pooled_kernel(const float* __restrict__ x,
                              float* __restrict__ out) {
    int i = blockIdx.x * blockDim.x + threadIdx.x;   // 0..BATCH*DMODEL-1
    if (i >= BATCH * DMODEL) return;
    int b = i / DMODEL, d = i % DMODEL;
    out[i] = x[((long)b * NSEQ + (NSEQ - 1)) * DMODEL + d];
}

// ---------------- generic fp32 GEMM -----------------------------------------
// C[M,N] = epilogue( A_eff[M,K] * B_eff[K,N] )
//   AKM=true : A stored [M,K] row-major (lda=K)  -> transpose into As[k][m]
//   AKM=false: A stored [K,M] row-major (lda=M)  -> direct As[k][m]
//   BKM=true : B stored [N,K] row-major (ldb=K)  -> transpose into Bs[k][n]
//   BKM=false: B stored [K,N] row-major (ldb=N)  -> direct Bs[k][n]
// epilogue: optional rowdiv (C /= rowdiv[m]), optional bias[n], optional elu+1
#define BM 128
#define BN 128
#define BK 16

template<bool AKM, bool BKM>
__global__ __launch_bounds__(256, 2)
void sgemm_kernel(int M, int N, int K,
                  const float* __restrict__ A, int lda, long sA,
                  const float* __restrict__ Bm, int ldb, long sB,
                  float* __restrict__ C, int ldc, long sC,
                  const float* __restrict__ bias,
                  const float* __restrict__ rowdiv, long sR,
                  int act)
{
    __shared__ float As[BK][BM + 4];
    __shared__ float Bs[BK][BN + 4];

    int tid = threadIdx.x;
    int tx = tid & 15, ty = tid >> 4;
    int mBase = blockIdx.y * BM;
    int nBase = blockIdx.x * BN;
    int zb = blockIdx.z;
    A  += (long)zb * sA;
    Bm += (long)zb * sB;
    C  += (long)zb * sC;
    if (rowdiv) rowdiv += (long)zb * sR;

    float acc[8][8];
    #pragma unroll
    for (int i = 0; i < 8; i++)
        #pragma unroll
        for (int j = 0; j < 8; j++) acc[i][j] = 0.f;

    for (int k0 = 0; k0 < K; k0 += BK) {
        // ---- load A tile ----
        if (AKM) {
            #pragma unroll
            for (int it = 0; it < 2; it++) {
                int idx = tid + it * 256;
                int r  = idx >> 2;             // 0..127 (m within tile)
                int c4 = (idx & 3) << 2;       // 0,4,8,12 (k within tile)
                int gm = mBase + r;
                float4 v = make_float4(0.f, 0.f, 0.f, 0.f);
                if (gm < M) v = *(const float4*)(A + (long)gm * lda + k0 + c4);
                As[c4 + 0][r] = v.x; As[c4 + 1][r] = v.y;
                As[c4 + 2][r] = v.z; As[c4 + 3][r] = v.w;
            }
        } else {
            #pragma unroll
            for (int it = 0; it < 2; it++) {
                int idx = tid + it * 256;
                int kr = idx >> 5;             // 0..15
                int mc = (idx & 31) << 2;      // 0..124
                int gm = mBase + mc;
                float4 v = make_float4(0.f, 0.f, 0.f, 0.f);
                if (gm < M) v = *(const float4*)(A + (long)(k0 + kr) * lda + gm);
                *(float4*)&As[kr][mc] = v;
            }
        }
        // ---- load B tile ----
        if (BKM) {
            #pragma unroll
            for (int it = 0; it < 2; it++) {
                int idx = tid + it * 256;
                int r  = idx >> 2;             // 0..127 (n within tile)
                int c4 = (idx & 3) << 2;
                int gn = nBase + r;
                float4 v = make_float4(0.f, 0.f, 0.f, 0.f);
                if (gn < N) v = *(const float4*)(Bm + (long)gn * ldb + k0 + c4);
                Bs[c4 + 0][r] = v.x; Bs[c4 + 1][r] = v.y;
                Bs[c4 + 2][r] = v.z; Bs[c4 + 3][r] = v.w;
            }
        } else {
            #pragma unroll
            for (int it = 0; it < 2; it++) {
                int idx = tid + it * 256;
                int kr = idx >> 5;
                int nc = (idx & 31) << 2;
                int gn = nBase + nc;
                float4 v = make_float4(0.f, 0.f, 0.f, 0.f);
                if (gn + 3 < N) {
                    v = *(const float4*)(Bm + (long)(k0 + kr) * ldb + gn);
                } else if (gn < N) {
                    const float* p = Bm + (long)(k0 + kr) * ldb;
                    v.x = p[gn];
                    if (gn + 1 < N) v.y = p[gn + 1];
                    if (gn + 2 < N) v.z = p[gn + 2];
                }
                *(float4*)&Bs[kr][nc] = v;
            }
        }
        __syncthreads();
        // ---- compute ----
        #pragma unroll
        for (int kk = 0; kk < BK; kk++) {
            float af[8], bf[8];
            #pragma unroll
            for (int i = 0; i < 8; i++) af[i] = As[kk][ty * 8 + i];
            #pragma unroll
            for (int j = 0; j < 8; j++) bf[j] = Bs[kk][tx * 8 + j];
            #pragma unroll
            for (int i = 0; i < 8; i++)
                #pragma unroll
                for (int j = 0; j < 8; j++)
                    acc[i][j] = fmaf(af[i], bf[j], acc[i][j]);
        }
        __syncthreads();
    }

    // ---- epilogue ----
    #pragma unroll
    for (int i = 0; i < 8; i++) {
        int gm = mBase + ty * 8 + i;
        if (gm >= M) continue;
        float rs = 1.0f;
        if (rowdiv) rs = 1.0f / rowdiv[gm];
        #pragma unroll
        for (int j = 0; j < 8; j++) {
            int gn = nBase + tx * 8 + j;
            if (gn >= N) continue;
            float c = acc[i][j] * rs;
            if (bias) c += bias[gn];
            if (act) c = (c > 0.f) ? (c + 1.0f) : expf(c);
            C[(long)gm * ldc + gn] = c;
        }
    }
}

// ---------------- driver -----------------------------------------------------
extern "C" void kernel_launch(void* const* d_in, const int* in_sizes, int n_in,
                              void* d_out, int out_size) {
    const int*   ids = (const int*)  d_in[0];
    const float* emb = (const float*)d_in[1];
    const float* Wq  = (const float*)d_in[2];
    const float* bq  = (const float*)d_in[3];
    const float* Wk  = (const float*)d_in[4];
    const float* bk  = (const float*)d_in[5];
    const float* Wv  = (const float*)d_in[6];
    const float* bv  = (const float*)d_in[7];
    const float* Wo  = (const float*)d_in[8];
    const float* bo  = (const float*)d_in[9];
    const float* Wh  = (const float*)d_in[10];
    const float* bh  = (const float*)d_in[11];

    float* logits = (float*)d_out;
    float* pooled = logits + (long)MTOK * VOCAB;

    float *x, *q, *kbuf, *vbuf, *ctx, *kv, *ks, *z;
    cudaGetSymbolAddress((void**)&x,    g_x);
    cudaGetSymbolAddress((void**)&q,    g_q);
    cudaGetSymbolAddress((void**)&kbuf, g_k);
    cudaGetSymbolAddress((void**)&vbuf, g_v);
    cudaGetSymbolAddress((void**)&ctx,  g_ctx);
    cudaGetSymbolAddress((void**)&kv,   g_kv);
    cudaGetSymbolAddress((void**)&ks,   g_ks);
    cudaGetSymbolAddress((void**)&z,    g_z);

    // x = emb[ids]
    gather_kernel<<<MTOK, 256>>>(ids, emb, x);

    const long sTok = (long)NSEQ * DMODEL;   // per-batch token-matrix stride
    const long sKV  = (long)DMODEL * DMODEL;

    for (int l = 0; l < NLAYER; l++) {
        const float* wq = Wq + (long)l * DMODEL * DMODEL;
        const float* wk = Wk + (long)l * DMODEL * DMODEL;
        const float* wv = Wv + (long)l * DMODEL * DMODEL;
        const float* wo = Wo + (long)l * DMODEL * DMODEL;
        const float* bql = bq + (long)l * DMODEL;
        const float* bkl = bk + (long)l * DMODEL;
        const float* bvl = bv + (long)l * DMODEL;
        const float* bol = bo + (long)l * DMODEL;

        dim3 gQ(DMODEL / BN, MTOK / BM, 1);          // (8, 32)
        // Q = elu(x Wq^T + bq) + 1 ; K likewise ; V = x Wv^T + bv
        sgemm_kernel<true, true><<<gQ, 256>>>(MTOK, DMODEL, DMODEL,
            x, DMODEL, 0, wq, DMODEL, 0, q,    DMODEL, 0, bql, nullptr, 0, 1);
        sgemm_kernel<true, true><<<gQ, 256>>>(MTOK, DMODEL, DMODEL,
            x, DMODEL, 0, wk, DMODEL, 0, kbuf, DMODEL, 0, bkl, nullptr, 0, 1);
        sgemm_kernel<true, true><<<gQ, 256>>>(MTOK, DMODEL, DMODEL,
            x, DMODEL, 0, wv, DMODEL, 0, vbuf, DMODEL, 0, bvl, nullptr, 0, 0);

        // KV[b] = K[b]^T V[b]   (TN, reduction over NSEQ)
        dim3 gKV(DMODEL / BN, DMODEL / BM, BATCH);   // (8, 8, 2)
        sgemm_kernel<false, false><<<gKV, 256>>>(DMODEL, DMODEL, NSEQ,
            kbuf, DMODEL, sTok, vbuf, DMODEL, sTok, kv, DMODEL, sKV,
            nullptr, nullptr, 0, 0);

        // Ksum + eps
        ksum_kernel<<<dim3(DMODEL / 256, BATCH), 256>>>(kbuf, ks);
        // Z = Q . Ksum
        z_kernel<<<MTOK / 8, 256>>>(q, ks, z);

        // ctx[b] = (Q[b] @ KV[b]) / Z   (NN)
        dim3 gC(DMODEL / BN, NSEQ / BM, BATCH);      // (8, 16, 2)
        sgemm_kernel<true, false><<<gC, 256>>>(NSEQ, DMODEL, DMODEL,
            q, DMODEL, sTok, kv, DMODEL, sKV, ctx, DMODEL, sTok,
            nullptr, z, NSEQ, 0);

        // x = ctx Wo^T + bo
        sgemm_kernel<true, true><<<gQ, 256>>>(MTOK, DMODEL, DMODEL,
            ctx, DMODEL, 0, wo, DMODEL, 0, x, DMODEL, 0, bol, nullptr, 0, 0);
    }

    // logits = x W_head^T + b_head
    dim3 gH((VOCAB + BN - 1) / BN, MTOK / BM, 1);    // (393, 32)
    sgemm_kernel<true, true><<<gH, 256>>>(MTOK, VOCAB, DMODEL,
        x, DMODEL, 0, Wh, DMODEL, 0, logits, VOCAB, 0, bh, nullptr, 0, 0);

    // pooled = x[:, -1]
    pooled_kernel<<<(BATCH * DMODEL + 255) / 256, 256>>>(x, pooled);
}

// round 4
// speedup vs baseline: 2.8633x; 2.8612x over previous
#include <cuda_runtime.h>
#include <cuda_bf16.h>
#include <math.h>
#include <stdint.h>

#define BATCH 2
#define NSEQ  2048
#define DMODEL 1024
#define NLAYER 2
#define VOCAB 50257
#define EPS_F 1e-6f
#define MTOK (BATCH*NSEQ)          // 4096
#define NTILES_H 393               // ceil(50257/128)
#define NPAD_H (NTILES_H*128)      // 50304
#define K3D (3*DMODEL)             // 3072
#define K3N (3*NSEQ)               // 6144

// ---------------- scratch ----------------
__device__ float g_x  [MTOK*DMODEL];
__device__ float g_q  [MTOK*DMODEL];
__device__ float g_k  [MTOK*DMODEL];
__device__ float g_v  [MTOK*DMODEL];
__device__ float g_ctx[MTOK*DMODEL];
__device__ float g_W  [BATCH*DMODEL*DMODEL];
__device__ float g_ks [BATCH*DMODEL];
__device__ float g_z  [MTOK];

__device__ __align__(128) __nv_bfloat16 g_xs [(long)MTOK*K3D];
__device__ __align__(128) __nv_bfloat16 g_qs [(long)MTOK*K3D];
__device__ __align__(128) __nv_bfloat16 g_cts[(long)MTOK*K3D];
__device__ __align__(128) __nv_bfloat16 g_vts[(long)BATCH*DMODEL*K3N];
__device__ __align__(128) __nv_bfloat16 g_kts[(long)BATCH*DMODEL*K3N];
__device__ __align__(128) __nv_bfloat16 g_wbuf[(long)DMODEL*K3D];
__device__ __align__(128) __nv_bfloat16 g_Wsp[(long)BATCH*DMODEL*K3D];
__device__ __align__(128) __nv_bfloat16 g_whs[(long)NPAD_H*K3D];

// ---------------- helpers ----------------
__device__ __forceinline__ uint32_t smem_u32(const void* p){
    uint32_t a;
    asm("{ .reg .u64 t; cvta.to.shared.u64 t, %1; cvt.u32.u64 %0, t; }" : "=r"(a) : "l"(p));
    return a;
}
__device__ __forceinline__ void ldsm_x4(uint32_t* r, uint32_t addr){
    asm volatile("ldmatrix.sync.aligned.m8n8.x4.shared.b16 {%0,%1,%2,%3}, [%4];"
        : "=r"(r[0]), "=r"(r[1]), "=r"(r[2]), "=r"(r[3]) : "r"(addr));
}
__device__ __forceinline__ void mma_bf16(float* d, const uint32_t* a, uint32_t b0, uint32_t b1){
    asm volatile("mma.sync.aligned.m16n8k16.row.col.f32.bf16.bf16.f32 "
        "{%0,%1,%2,%3}, {%4,%5,%6,%7}, {%8,%9}, {%0,%1,%2,%3};"
        : "+f"(d[0]), "+f"(d[1]), "+f"(d[2]), "+f"(d[3])
        : "r"(a[0]), "r"(a[1]), "r"(a[2]), "r"(a[3]), "r"(b0), "r"(b1));
}
__device__ __forceinline__ void cp16(uint32_t saddr, const void* g){
    asm volatile("cp.async.cg.shared.global.L2::128B [%0], [%1], 16;" :: "r"(saddr), "l"(g));
}
#define CP_COMMIT() asm volatile("cp.async.commit_group;" ::: "memory")
#define CP_WAIT(n)  asm volatile("cp.async.wait_group %0;" :: "n"(n) : "memory")

// split fp32 -> (hi, lo) bf16
__device__ __forceinline__ void split8(const float* xv, uint4* hi, uint4* lo){
    __align__(16) __nv_bfloat16 h[8], l[8];
    #pragma unroll
    for (int j = 0; j < 8; j++) {
        h[j] = __float2bfloat16(xv[j]);
        l[j] = __float2bfloat16(xv[j] - __bfloat162float(h[j]));
    }
    *hi = *(const uint4*)h;
    *lo = *(const uint4*)l;
}

// ---------------- pack kernels ----------------
// A' = [Ah | Ah | Al] along K  (dst [Mr, 3Kd])
__global__ void pack_a_direct(const float* __restrict__ src, int Mr, int Kd,
                              __nv_bfloat16* __restrict__ dst) {
    int kUnits = Kd >> 3;
    long u = (long)blockIdx.x * blockDim.x + threadIdx.x;
    if (u >= (long)Mr * kUnits) return;
    int m  = (int)(u / kUnits);
    int ku = (int)(u % kUnits);
    const float4* s = (const float4*)(src + (long)m * Kd + ((long)ku << 3));
    float4 a = s[0], b = s[1];
    float xv[8] = {a.x, a.y, a.z, a.w, b.x, b.y, b.z, b.w};
    uint4 hi, lo; split8(xv, &hi, &lo);
    __nv_bfloat16* base = dst + (long)m * (3*Kd) + ((long)ku << 3);
    *(uint4*)(base)          = hi;
    *(uint4*)(base + Kd)     = hi;
    *(uint4*)(base + 2*Kd)   = lo;
}

// B' = [Bh | Bl | Bh] along K, zero-pad rows to Npad  (dst [Npad, 3Kd]); z-batched
__global__ void pack_b_direct(const float* __restrict__ src, int Nr, int Kd, int Npad,
                              __nv_bfloat16* __restrict__ dst, long sSrcZ, long sDstZ) {
    int zb = blockIdx.y;
    src += (long)zb * sSrcZ; dst += (long)zb * sDstZ;
    int kUnits = Kd >> 3;
    long u = (long)blockIdx.x * blockDim.x + threadIdx.x;
    if (u >= (long)Npad * kUnits) return;
    int n  = (int)(u / kUnits);
    int ku = (int)(u % kUnits);
    float xv[8] = {0.f,0.f,0.f,0.f,0.f,0.f,0.f,0.f};
    if (n < Nr) {
        const float4* s = (const float4*)(src + (long)n * Kd + ((long)ku << 3));
        float4 a = s[0], b = s[1];
        xv[0]=a.x; xv[1]=a.y; xv[2]=a.z; xv[3]=a.w; xv[4]=b.x; xv[5]=b.y; xv[6]=b.z; xv[7]=b.w;
    }
    uint4 hi, lo; split8(xv, &hi, &lo);
    __nv_bfloat16* base = dst + (long)n * (3*Kd) + ((long)ku << 3);
    *(uint4*)(base)          = hi;
    *(uint4*)(base + Kd)     = lo;
    *(uint4*)(base + 2*Kd)   = hi;
}

// transposed A' : effective A[m,k] = src[k*Mdst + m]; z-batched
__global__ void pack_a_trans(const float* __restrict__ src, int Mdst, int Kd,
                             __nv_bfloat16* __restrict__ dst, long sSrcZ, long sDstZ) {
    int zb = blockIdx.y;
    src += (long)zb * sSrcZ; dst += (long)zb * sDstZ;
    int kUnits = Kd >> 3;
    long u = (long)blockIdx.x * blockDim.x + threadIdx.x;
    if (u >= (long)Mdst * kUnits) return;
    int m  = (int)(u % Mdst);
    int ku = (int)(u / Mdst);
    float xv[8];
    #pragma unroll
    for (int j = 0; j < 8; j++) xv[j] = src[((long)(ku * 8 + j)) * Mdst + m];
    uint4 hi, lo; split8(xv, &hi, &lo);
    __nv_bfloat16* base = dst + (long)m * (3*Kd) + ((long)ku << 3);
    *(uint4*)(base)          = hi;
    *(uint4*)(base + Kd)     = hi;
    *(uint4*)(base + 2*Kd)   = lo;
}

// transposed B' : effective B[n,k] = src[k*Ndst + n]; z-batched
__global__ void pack_b_trans(const float* __restrict__ src, int Ndst, int Kd,
                             __nv_bfloat16* __restrict__ dst, long sSrcZ, long sDstZ) {
    int zb = blockIdx.y;
    src += (long)zb * sSrcZ; dst += (long)zb * sDstZ;
    int kUnits = Kd >> 3;
    long u = (long)blockIdx.x * blockDim.x + threadIdx.x;
    if (u >= (long)Ndst * kUnits) return;
    int n  = (int)(u % Ndst);
    int ku = (int)(u / Ndst);
    float xv[8];
    #pragma unroll
    for (int j = 0; j < 8; j++) xv[j] = src[((long)(ku * 8 + j)) * Ndst + n];
    uint4 hi, lo; split8(xv, &hi, &lo);
    __nv_bfloat16* base = dst + (long)n * (3*Kd) + ((long)ku << 3);
    *(uint4*)(base)          = hi;
    *(uint4*)(base + Kd)     = lo;
    *(uint4*)(base + 2*Kd)   = hi;
}

// ---------------- HMMA GEMM ----------------
// C[M,N] = act( A'[M,K3] . B'[N,K3]^T / rowdiv + bias )
// CTA tile 128x128, BK=64 bf16, 3-stage cp.async pipeline, 8 warps (2x4), warp 64x32.
#define STAGES 3
#define STAGE_BYTES 32768
#define GEMM_SMEM (STAGES*STAGE_BYTES)

__global__ __launch_bounds__(256, 2)
void hgemm_kernel(const __nv_bfloat16* __restrict__ A,
                  const __nv_bfloat16* __restrict__ B,
                  long sA, long sB,
                  int K3, int N,
                  float* __restrict__ C, int ldc, long sC,
                  const float* __restrict__ bias,
                  const float* __restrict__ rowdiv, long sR,
                  int act)
{
    extern __shared__ char smem[];
    uint32_t sbase = smem_u32(smem);
    int tid = threadIdx.x;
    int lane = tid & 31, wid = tid >> 5;
    int wm = wid >> 2, wn = wid & 3;     // 2 x 4 warps
    int mBase = blockIdx.x * 128;        // M fastest -> B-tile L2 reuse
    int nBase = blockIdx.y * 128;
    int zb = blockIdx.z;
    A += (long)zb * sA; B += (long)zb * sB; C += (long)zb * sC;
    if (rowdiv) rowdiv += (long)zb * sR;

    const char* aG = (const char*)(A + (long)mBase * K3);
    const char* bG = (const char*)(B + (long)nBase * K3);
    long ldg = (long)K3 * 2;

    int lr = tid >> 3;          // 0..31 row-in-pass
    int la = tid & 7;           // 16B atom in 128B row

    float acc[4][4][4];
    #pragma unroll
    for (int i = 0; i < 4; i++)
        #pragma unroll
        for (int j = 0; j < 4; j++)
            #pragma unroll
            for (int e = 0; e < 4; e++) acc[i][j][e] = 0.f;

    int nK = K3 >> 6;

    // ---- prologue: load STAGES-1 chunks ----
    #pragma unroll
    for (int s = 0; s < STAGES-1; s++) {
        uint32_t aS = sbase + s*STAGE_BYTES;
        uint32_t bS = aS + 16384;
        const char* ag = aG + (long)s*128;
        const char* bg = bG + (long)s*128;
        #pragma unroll
        for (int p = 0; p < 4; p++) {
            int r = lr + p*32;
            uint32_t so = (uint32_t)r*128 + 16u*(uint32_t)(la ^ (r & 7));
            cp16(aS + so, ag + (long)r*ldg + la*16);
            cp16(bS + so, bg + (long)r*ldg + la*16);
        }
        CP_COMMIT();
    }

    for (int i = 0; i < nK; i++) {
        CP_WAIT(STAGES-2);
        __syncthreads();
        int nc = i + STAGES - 1;
        if (nc < nK) {
            int s = nc % STAGES;
            uint32_t aS = sbase + s*STAGE_BYTES;
            uint32_t bS = aS + 16384;
            const char* ag = aG + (long)nc*128;
            const char* bg = bG + (long)nc*128;
            #pragma unroll
            for (int p = 0; p < 4; p++) {
                int r = lr + p*32;
                uint32_t so = (uint32_t)r*128 + 16u*(uint32_t)(la ^ (r & 7));
                cp16(aS + so, ag + (long)r*ldg + la*16);
                cp16(bS + so, bg + (long)r*ldg + la*16);
            }
        }
        CP_COMMIT();

        // ---- compute chunk i ----
        int cs = i % STAGES;
        uint32_t aS = sbase + cs*STAGE_BYTES;
        uint32_t bS = aS + 16384;
        #pragma unroll
        for (int kt = 0; kt < 4; kt++) {
            uint32_t af[4][4];
            #pragma unroll
            for (int mt = 0; mt < 4; mt++) {
                int row = wm*64 + mt*16 + (lane & 15);
                int a = kt*2 + (lane >> 4);
                ldsm_x4(af[mt], aS + (uint32_t)row*128 + 16u*(uint32_t)(a ^ (row & 7)));
            }
            uint32_t bf2[2][4];
            #pragma unroll
            for (int np = 0; np < 2; np++) {
                int row = wn*32 + np*16 + ((lane >> 4) & 1)*8 + (lane & 7);
                int a = kt*2 + ((lane >> 3) & 1);
                ldsm_x4(bf2[np], bS + (uint32_t)row*128 + 16u*(uint32_t)(a ^ (row & 7)));
            }
            #pragma unroll
            for (int mt = 0; mt < 4; mt++)
                #pragma unroll
                for (int nt = 0; nt < 4; nt++)
                    mma_bf16(acc[mt][nt], af[mt], bf2[nt>>1][(nt&1)*2], bf2[nt>>1][(nt&1)*2+1]);
        }
    }

    // ---- epilogue ----
    int mW = mBase + wm*64;
    int nW = nBase + wn*32;
    #pragma unroll
    for (int mt = 0; mt < 4; mt++) {
        int r0 = mW + mt*16 + (lane >> 2);
        int r1 = r0 + 8;
        float rs0 = 1.f, rs1 = 1.f;
        if (rowdiv) { rs0 = 1.f / rowdiv[r0]; rs1 = 1.f / rowdiv[r1]; }
        float* c0 = C + (long)r0 * ldc;
        float* c1 = C + (long)r1 * ldc;
        #pragma unroll
        for (int nt = 0; nt < 4; nt++) {
            int cn = nW + nt*8 + 2*(lane & 3);
            const float* dv = acc[mt][nt];
            #pragma unroll
            for (int e = 0; e < 2; e++) {
                int col = cn + e;
                if (col < N) {
                    float b0 = bias ? bias[col] : 0.f;
                    float v0 = dv[e]   * rs0 + b0;
                    float v1 = dv[e+2] * rs1 + b0;
                    if (act) {
                        v0 = (v0 > 0.f) ? v0 + 1.0f : expf(v0);
                        v1 = (v1 > 0.f) ? v1 + 1.0f : expf(v1);
                    }
                    c0[col] = v0;
                    c1[col] = v1;
                }
            }
        }
    }
}

// ---------------- small kernels ----------------
__global__ void gather_kernel(const int* __restrict__ ids,
                              const float* __restrict__ emb,
                              float* __restrict__ x) {
    int row = blockIdx.x;
    int id  = ids[row];
    const float4* src = (const float4*)(emb + (long)id * DMODEL);
    float4*       dst = (float4*)(x + (long)row * DMODEL);
    for (int i = threadIdx.x; i < DMODEL/4; i += blockDim.x) dst[i] = src[i];
}
__global__ void ksum_kernel(const float* __restrict__ Kbuf, float* __restrict__ ks) {
    int d = blockIdx.x * 256 + threadIdx.x;
    int b = blockIdx.y;
    const float* p = Kbuf + (long)b * NSEQ * DMODEL + d;
    float acc = 0.f;
    #pragma unroll 8
    for (int n = 0; n < NSEQ; n++) acc += p[(long)n * DMODEL];
    ks[b * DMODEL + d] = acc + EPS_F;
}
__global__ void z_kernel(const float* __restrict__ Q, const float* __restrict__ ks,
                         float* __restrict__ z) {
    int row  = blockIdx.x * 8 + (threadIdx.x >> 5);
    int lane = threadIdx.x & 31;
    int b    = row / NSEQ;
    const float* q = Q  + (long)row * DMODEL;
    const float* s = ks + (long)b   * DMODEL;
    float acc = 0.f;
    #pragma unroll 4
    for (int i = lane; i < DMODEL; i += 32) acc += q[i] * s[i];
    #pragma unroll
    for (int o = 16; o; o >>= 1) acc += __shfl_xor_sync(0xffffffffu, acc, o);
    if (lane == 0) z[row] = acc;
}
__global__ void pooled_kernel(const float* __restrict__ x, float* __restrict__ out) {
    int i = blockIdx.x * blockDim.x + threadIdx.x;
    if (i >= BATCH * DMODEL) return;
    int b = i / DMODEL, d = i % DMODEL;
    out[i] = x[((long)b * NSEQ + (NSEQ - 1)) * DMODEL + d];
}

// ---------------- driver ----------------
static inline long cdivl(long a, long b){ return (a + b - 1) / b; }

extern "C" void kernel_launch(void* const* d_in, const int* in_sizes, int n_in,
                              void* d_out, int out_size) {
    const int*   ids = (const int*)  d_in[0];
    const float* emb = (const float*)d_in[1];
    const float* Wq  = (const float*)d_in[2];
    const float* bq  = (const float*)d_in[3];
    const float* Wk  = (const float*)d_in[4];
    const float* bk  = (const float*)d_in[5];
    const float* Wv  = (const float*)d_in[6];
    const float* bv  = (const float*)d_in[7];
    const float* Wo  = (const float*)d_in[8];
    const float* bo  = (const float*)d_in[9];
    const float* Wh  = (const float*)d_in[10];
    const float* bh  = (const float*)d_in[11];

    float* logits = (float*)d_out;
    float* pooled = logits + (long)MTOK * VOCAB;

    float *x, *q, *kbuf, *vbuf, *ctx, *Wf, *ks, *z;
    __nv_bfloat16 *xs, *qs, *cts, *vts, *kts, *wbuf, *Wsp, *whs;
    cudaGetSymbolAddress((void**)&x,    g_x);
    cudaGetSymbolAddress((void**)&q,    g_q);
    cudaGetSymbolAddress((void**)&kbuf, g_k);
    cudaGetSymbolAddress((void**)&vbuf, g_v);
    cudaGetSymbolAddress((void**)&ctx,  g_ctx);
    cudaGetSymbolAddress((void**)&Wf,   g_W);
    cudaGetSymbolAddress((void**)&ks,   g_ks);
    cudaGetSymbolAddress((void**)&z,    g_z);
    cudaGetSymbolAddress((void**)&xs,   g_xs);
    cudaGetSymbolAddress((void**)&qs,   g_qs);
    cudaGetSymbolAddress((void**)&cts,  g_cts);
    cudaGetSymbolAddress((void**)&vts,  g_vts);
    cudaGetSymbolAddress((void**)&kts,  g_kts);
    cudaGetSymbolAddress((void**)&wbuf, g_wbuf);
    cudaGetSymbolAddress((void**)&Wsp,  g_Wsp);
    cudaGetSymbolAddress((void**)&whs,  g_whs);

    cudaFuncSetAttribute(hgemm_kernel, cudaFuncAttributeMaxDynamicSharedMemorySize, GEMM_SMEM);

    gather_kernel<<<MTOK, 256>>>(ids, emb, x);

    // head weights -> B' panels (once)
    {
        long total = (long)NPAD_H * (DMODEL/8);
        pack_b_direct<<<(unsigned)cdivl(total,256), 256>>>(Wh, VOCAB, DMODEL, NPAD_H, whs, 0, 0);
    }

    const long sTok = (long)NSEQ * DMODEL;
    const long sW   = (long)DMODEL * DMODEL;
    const long aTU  = (long)MTOK * (DMODEL/8);
    const long wTU  = (long)DMODEL * (DMODEL/8);

    for (int l = 0; l < NLAYER; l++) {
        const float* wq = Wq + (long)l * sW;
        const float* wk = Wk + (long)l * sW;
        const float* wv = Wv + (long)l * sW;
        const float* wo = Wo + (long)l * sW;
        const float* bql = bq + (long)l * DMODEL;
        const float* bkl = bk + (long)l * DMODEL;
        const float* bvl = bv + (long)l * DMODEL;
        const float* bol = bo + (long)l * DMODEL;

        pack_a_direct<<<(unsigned)cdivl(aTU,256), 256>>>(x, MTOK, DMODEL, xs);

        dim3 gQKV(32, 8, 1);   // M-tiles x N-tiles
        pack_b_direct<<<(unsigned)cdivl(wTU,256), 256>>>(wq, DMODEL, DMODEL, DMODEL, wbuf, 0, 0);
        hgemm_kernel<<<gQKV, 256, GEMM_SMEM>>>(xs, wbuf, 0, 0, K3D, DMODEL,
            q, DMODEL, 0, bql, nullptr, 0, 1);
        pack_b_direct<<<(unsigned)cdivl(wTU,256), 256>>>(wk, DMODEL, DMODEL, DMODEL, wbuf, 0, 0);
        hgemm_kernel<<<gQKV, 256, GEMM_SMEM>>>(xs, wbuf, 0, 0, K3D, DMODEL,
            kbuf, DMODEL, 0, bkl, nullptr, 0, 1);
        pack_b_direct<<<(unsigned)cdivl(wTU,256), 256>>>(wv, DMODEL, DMODEL, DMODEL, wbuf, 0, 0);
        hgemm_kernel<<<gQKV, 256, GEMM_SMEM>>>(xs, wbuf, 0, 0, K3D, DMODEL,
            vbuf, DMODEL, 0, bvl, nullptr, 0, 0);

        // transpose-pack: Vt as A' (M=DMODEL, K=NSEQ), Kt as B'
        {
            long tu = (long)DMODEL * (NSEQ/8);
            pack_a_trans<<<dim3((unsigned)cdivl(tu,256), BATCH), 256>>>(vbuf, DMODEL, NSEQ,
                vts, sTok, (long)DMODEL*K3N);
            pack_b_trans<<<dim3((unsigned)cdivl(tu,256), BATCH), 256>>>(kbuf, DMODEL, NSEQ,
                kts, sTok, (long)DMODEL*K3N);
        }
        // Wf[e,d] = sum_n V[n,e] K[n,d]
        hgemm_kernel<<<dim3(8, 8, BATCH), 256, GEMM_SMEM>>>(vts, kts,
            (long)DMODEL*K3N, (long)DMODEL*K3N, K3N, DMODEL,
            Wf, DMODEL, sW, nullptr, nullptr, 0, 0);

        ksum_kernel<<<dim3(DMODEL/256, BATCH), 256>>>(kbuf, ks);
        z_kernel<<<MTOK/8, 256>>>(q, ks, z);

        pack_a_direct<<<(unsigned)cdivl(aTU,256), 256>>>(q, MTOK, DMODEL, qs);
        pack_b_direct<<<dim3((unsigned)cdivl(wTU,256), BATCH), 256>>>(Wf, DMODEL, DMODEL, DMODEL,
            Wsp, sW, (long)DMODEL*K3D);

        // ctx[b][n,e] = (sum_d Q[n,d] Wf[e,d]) / Z[b,n]
        hgemm_kernel<<<dim3(16, 8, BATCH), 256, GEMM_SMEM>>>(qs, Wsp,
            (long)NSEQ*K3D, (long)DMODEL*K3D, K3D, DMODEL,
            ctx, DMODEL, sTok, nullptr, z, NSEQ, 0);

        // x = ctx @ Wo^T + bo
        pack_a_direct<<<(unsigned)cdivl(aTU,256), 256>>>(ctx, MTOK, DMODEL, cts);
        pack_b_direct<<<(unsigned)cdivl(wTU,256), 256>>>(wo, DMODEL, DMODEL, DMODEL, wbuf, 0, 0);
        hgemm_kernel<<<gQKV, 256, GEMM_SMEM>>>(cts, wbuf, 0, 0, K3D, DMODEL,
            x, DMODEL, 0, bol, nullptr, 0, 0);
    }

    // logits = x @ Wh^T + bh
    pack_a_direct<<<(unsigned)cdivl(aTU,256), 256>>>(x, MTOK, DMODEL, xs);
    hgemm_kernel<<<dim3(32, NTILES_H, 1), 256, GEMM_SMEM>>>(xs, whs, 0, 0, K3D, VOCAB,
        logits, VOCAB, 0, bh, nullptr, 0, 0);

    pooled_kernel<<<(BATCH * DMODEL + 255) / 256, 256>>>(x, pooled);
}